// round 1
// baseline (speedup 1.0000x reference)
#include <cuda_runtime.h>

#define EPSF 1e-6f

constexpr int cV = 128, cK = 32, cC = 256;
constexpr int cL = 4, cN = 4096, cF = 16;
constexpr int cE = 8192, cB = 512;
constexpr int cB4 = cB / 4;   // 128 float4 groups per row

// ---- scratch (static __device__ per allocation rules) ----
__device__ __align__(16) float d_lwin[cV * cK * cC];   // 4 MB
__device__ __align__(16) float d_lwsum[cL * cN * cF];  // 1 MB
__device__ __align__(16) float d_lr[cN];               // 16 KB
__device__ __align__(16) float d_nmA[cN * cB];         // 8 MB
__device__ __align__(16) float d_nmB[cN * cB];         // 8 MB
__device__ __align__(16) float d_em[cE * cB];          // 16 MB

// ------------------------------------------------------------------
// 1) normalize input params: lwin = log(p+eps) - LSE_C  (one warp/row)
// ------------------------------------------------------------------
__global__ void k_norm_input(const float* __restrict__ ip) {
    int w    = (blockIdx.x * blockDim.x + threadIdx.x) >> 5;  // row 0..V*K-1
    int lane = threadIdx.x & 31;
    const float* row = ip + w * cC;
    float v[8];
    float m = -1e30f;
#pragma unroll
    for (int i = 0; i < 8; i++) {
        v[i] = __logf(row[lane + i * 32] + EPSF);
        m    = fmaxf(m, v[i]);
    }
#pragma unroll
    for (int o = 16; o; o >>= 1) m = fmaxf(m, __shfl_xor_sync(0xffffffffu, m, o));
    float s = 0.f;
#pragma unroll
    for (int i = 0; i < 8; i++) s += __expf(v[i] - m);
#pragma unroll
    for (int o = 16; o; o >>= 1) s += __shfl_xor_sync(0xffffffffu, s, o);
    float lse = m + __logf(s);
#pragma unroll
    for (int i = 0; i < 8; i++) d_lwin[w * cC + lane + i * 32] = v[i] - lse;
}

// ------------------------------------------------------------------
// 2) normalize sum params: one thread per (l,n) row of F=16
// ------------------------------------------------------------------
__global__ void k_norm_sum(const float* __restrict__ sp) {
    int r = blockIdx.x * blockDim.x + threadIdx.x;  // 0..L*N-1
    const float4* s4 = reinterpret_cast<const float4*>(sp) + r * 4;
    float v[16];
#pragma unroll
    for (int i = 0; i < 4; i++) {
        float4 x = s4[i];
        v[i * 4 + 0] = __logf(x.x + EPSF);
        v[i * 4 + 1] = __logf(x.y + EPSF);
        v[i * 4 + 2] = __logf(x.z + EPSF);
        v[i * 4 + 3] = __logf(x.w + EPSF);
    }
    float m = v[0];
#pragma unroll
    for (int i = 1; i < 16; i++) m = fmaxf(m, v[i]);
    float s = 0.f;
#pragma unroll
    for (int i = 0; i < 16; i++) s += __expf(v[i] - m);
    float lse = m + __logf(s);
    float4* dst = reinterpret_cast<float4*>(d_lwsum) + r * 4;
#pragma unroll
    for (int i = 0; i < 4; i++) {
        float4 o;
        o.x = v[i * 4 + 0] - lse;
        o.y = v[i * 4 + 1] - lse;
        o.z = v[i * 4 + 2] - lse;
        o.w = v[i * 4 + 3] - lse;
        dst[i] = o;
    }
}

// ------------------------------------------------------------------
// 3) normalize root params: single block, LSE over N=4096
// ------------------------------------------------------------------
__global__ void k_norm_root(const float* __restrict__ rp) {
    __shared__ float red[1024];
    int t = threadIdx.x;  // 1024 threads
    float v[4];
    float m = -1e30f;
#pragma unroll
    for (int i = 0; i < 4; i++) {
        v[i] = __logf(rp[t + i * 1024] + EPSF);
        m    = fmaxf(m, v[i]);
    }
    red[t] = m;
    __syncthreads();
    for (int o = 512; o; o >>= 1) {
        if (t < o) red[t] = fmaxf(red[t], red[t + o]);
        __syncthreads();
    }
    m = red[0];
    __syncthreads();
    float s = 0.f;
#pragma unroll
    for (int i = 0; i < 4; i++) s += __expf(v[i] - m);
    red[t] = s;
    __syncthreads();
    for (int o = 512; o; o >>= 1) {
        if (t < o) red[t] += red[t + o];
        __syncthreads();
    }
    float lse = m + __logf(red[0]);
#pragma unroll
    for (int i = 0; i < 4; i++) d_lr[t + i * 1024] = v[i] - lse;
}

// ------------------------------------------------------------------
// 4) input layer gather: nmA[(v*K+k)*B + b] = lwin[v,k,inputs[b,v]]
//    one block per v; lwin[v] row (32KB) staged in SMEM
// ------------------------------------------------------------------
__global__ void __launch_bounds__(512) k_input_gather(const int* __restrict__ inputs) {
    __shared__ float s_lw[cK * cC];  // 32 KB
    int v = blockIdx.x;
    int t = threadIdx.x;  // 512 threads, one per batch b
    for (int i = t; i < cK * cC; i += 512) s_lw[i] = d_lwin[v * cK * cC + i];
    int x = inputs[t * cV + v];
    __syncthreads();
#pragma unroll
    for (int k = 0; k < cK; k++) d_nmA[(v * cK + k) * cB + t] = s_lw[k * cC + x];
}

// ------------------------------------------------------------------
// 5) product layer: em[e][:] = nm[c0][:] + nm[c1][:]  (coalesced float4)
// ------------------------------------------------------------------
__global__ void __launch_bounds__(128) k_em(const int* __restrict__ pc, int l, int src) {
    const float* nm = src ? d_nmB : d_nmA;
    int e = blockIdx.x;
    int t = threadIdx.x;
    int c0 = __ldg(pc + (l * cE + e) * 2);
    int c1 = __ldg(pc + (l * cE + e) * 2 + 1);
    float4 a = reinterpret_cast<const float4*>(nm + c0 * cB)[t];
    float4 b = reinterpret_cast<const float4*>(nm + c1 * cB)[t];
    float4 o;
    o.x = a.x + b.x; o.y = a.y + b.y; o.z = a.z + b.z; o.w = a.w + b.w;
    reinterpret_cast<float4*>(d_em)[e * cB4 + t] = o;
}

// ------------------------------------------------------------------
// 6) sum layer: nm_out[n][:] = LSE_f( em[sci[l,n,f]][:] + lwsum[l,n,f] )
//    two-pass max-trick with all F=16 float4 values held in registers
// ------------------------------------------------------------------
__global__ void __launch_bounds__(128) k_sum(const int* __restrict__ sci, int l, int dst) {
    float* nm_out = dst ? d_nmB : d_nmA;
    int n = blockIdx.x;
    int t = threadIdx.x;
    __shared__ int   s_e[cF];
    __shared__ float s_w[cF];
    if (t < cF) {
        s_e[t] = sci[(l * cN + n) * cF + t];
        s_w[t] = d_lwsum[(l * cN + n) * cF + t];
    }
    __syncthreads();
    float4 val[cF];
#pragma unroll
    for (int f = 0; f < cF; f++) {
        float4 x = reinterpret_cast<const float4*>(d_em)[s_e[f] * cB4 + t];
        float  w = s_w[f];
        val[f].x = x.x + w; val[f].y = x.y + w; val[f].z = x.z + w; val[f].w = x.w + w;
    }
    float4 m = val[0];
#pragma unroll
    for (int f = 1; f < cF; f++) {
        m.x = fmaxf(m.x, val[f].x); m.y = fmaxf(m.y, val[f].y);
        m.z = fmaxf(m.z, val[f].z); m.w = fmaxf(m.w, val[f].w);
    }
    float4 s = make_float4(0.f, 0.f, 0.f, 0.f);
#pragma unroll
    for (int f = 0; f < cF; f++) {
        s.x += __expf(val[f].x - m.x); s.y += __expf(val[f].y - m.y);
        s.z += __expf(val[f].z - m.z); s.w += __expf(val[f].w - m.w);
    }
    float4 o;
    o.x = m.x + __logf(s.x); o.y = m.y + __logf(s.y);
    o.z = m.z + __logf(s.z); o.w = m.w + __logf(s.w);
    reinterpret_cast<float4*>(nm_out)[n * cB4 + t] = o;
}

// ------------------------------------------------------------------
// 7) root: out[b] = LSE_n( nm[n][b] + lr[n] ); one block per float4 batch group
// ------------------------------------------------------------------
__global__ void __launch_bounds__(128) k_final(float* __restrict__ out, int src) {
    const float4* nm = reinterpret_cast<const float4*>(src ? d_nmB : d_nmA);
    __shared__ float4 red[128];
    int g = blockIdx.x;   // 0..127 batch group
    int t = threadIdx.x;  // 128 threads over n
    float4 m = make_float4(-1e30f, -1e30f, -1e30f, -1e30f);
    for (int n = t; n < cN; n += 128) {
        float  lr = d_lr[n];
        float4 v  = nm[n * cB4 + g];
        m.x = fmaxf(m.x, v.x + lr); m.y = fmaxf(m.y, v.y + lr);
        m.z = fmaxf(m.z, v.z + lr); m.w = fmaxf(m.w, v.w + lr);
    }
    red[t] = m;
    __syncthreads();
    for (int o = 64; o; o >>= 1) {
        if (t < o) {
            float4 a = red[t], b = red[t + o];
            a.x = fmaxf(a.x, b.x); a.y = fmaxf(a.y, b.y);
            a.z = fmaxf(a.z, b.z); a.w = fmaxf(a.w, b.w);
            red[t] = a;
        }
        __syncthreads();
    }
    m = red[0];
    __syncthreads();
    float4 s = make_float4(0.f, 0.f, 0.f, 0.f);
    for (int n = t; n < cN; n += 128) {
        float  lr = d_lr[n];
        float4 v  = nm[n * cB4 + g];
        s.x += __expf(v.x + lr - m.x); s.y += __expf(v.y + lr - m.y);
        s.z += __expf(v.z + lr - m.z); s.w += __expf(v.w + lr - m.w);
    }
    red[t] = s;
    __syncthreads();
    for (int o = 64; o; o >>= 1) {
        if (t < o) {
            float4 a = red[t], b = red[t + o];
            a.x += b.x; a.y += b.y; a.z += b.z; a.w += b.w;
            red[t] = a;
        }
        __syncthreads();
    }
    if (t == 0) {
        float4 r = red[0];
        out[g * 4 + 0] = m.x + __logf(r.x);
        out[g * 4 + 1] = m.y + __logf(r.y);
        out[g * 4 + 2] = m.z + __logf(r.z);
        out[g * 4 + 3] = m.w + __logf(r.w);
    }
}

// ------------------------------------------------------------------
extern "C" void kernel_launch(void* const* d_in, const int* in_sizes, int n_in,
                              void* d_out, int out_size) {
    const int*   inputs = (const int*)d_in[0];    // (B, V)
    const int*   pc     = (const int*)d_in[1];    // (L, E, 2)
    const int*   sci    = (const int*)d_in[2];    // (L, N, F)
    const float* ip     = (const float*)d_in[3];  // (V, K, C)
    const float* sp     = (const float*)d_in[4];  // (L, N, F)
    const float* rp     = (const float*)d_in[5];  // (N,)
    float* out = (float*)d_out;                   // (B,)

    k_norm_input<<<512, 256>>>(ip);   // 4096 warps, one per (v,k)
    k_norm_sum<<<128, 128>>>(sp);     // 16384 threads, one per (l,n)
    k_norm_root<<<1, 1024>>>(rp);
    k_input_gather<<<cV, 512>>>(inputs);  // writes d_nmA

    int src = 0;  // 0 = nmA, 1 = nmB
    for (int l = 0; l < cL; l++) {
        k_em<<<cE, 128>>>(pc, l, src);
        k_sum<<<cN, 128>>>(sci, l, 1 - src);
        src = 1 - src;
    }
    k_final<<<cB4, 128>>>(out, src);
}